// round 2
// baseline (speedup 1.0000x reference)
#include <cuda_runtime.h>
#include <math.h>

// Problem constants (B=16, L=256)
#define LQ 256
#define BQ 16
#define CHART (BQ * LQ * LQ)
#define NT 512            // threads per block
#define MAXB 1024         // max blocks we size scratch for

// Scratch (no allocation allowed -> __device__ globals)
// g_S  : inside chart s[b,i,j]           (row-major)
// g_ST : transposed inside chart         sT[b,j,i] = s[b,i,j]
// g_BL : outside credit as LEFT child    [b,i,k]
// g_BT : outside credit as RIGHT child   (transposed) [b,j,k+1]
// marginal(i,j) = g_BL[b,i,j] + g_BT[b,j,i] (+1 at root (0,len-1))
__device__ float g_S[CHART];
__device__ float g_ST[CHART];
__device__ float g_BL[CHART];
__device__ float g_BT[CHART];
__device__ int   g_lens[BQ];
__device__ double g_part[MAXB * 3];

// software grid barrier state (gen persists across graph replays; equality-spin is safe)
__device__ unsigned g_arrive;
__device__ volatile unsigned g_gen;

__device__ __forceinline__ void grid_sync(int nb) {
    __threadfence();      // every thread makes its writes visible device-wide
    __syncthreads();
    if (threadIdx.x == 0) {
        unsigned gen = g_gen;
        if (atomicAdd(&g_arrive, 1u) == (unsigned)nb - 1u) {
            g_arrive = 0u;
            __threadfence();
            g_gen = gen + 1u;
        } else {
            while (g_gen == gen) __nanosleep(64);
        }
        __threadfence();
    }
    __syncthreads();
}

__device__ __forceinline__ float warp_max(float v) {
#pragma unroll
    for (int o = 16; o; o >>= 1) v = fmaxf(v, __shfl_xor_sync(0xffffffffu, v, o));
    return v;
}
__device__ __forceinline__ float warp_sum(float v) {
#pragma unroll
    for (int o = 16; o; o >>= 1) v += __shfl_xor_sync(0xffffffffu, v, o);
    return v;
}

// ---------------------------------------------------------------------------
// One persistent kernel: init -> inside (255 steps) -> outside (255 steps)
// -> fused loss reduction. Grid barriers between dependent phases/steps.
__global__ void __launch_bounds__(NT)
k_mega(const float* __restrict__ lg,
       const float* __restrict__ ph, const float* __restrict__ pt,
       const float* __restrict__ ph_arc,
       const int* __restrict__ spans_ind,
       const int* __restrict__ ph_ind, const int* __restrict__ pt_ind,
       const unsigned char* __restrict__ mspanB, const int* __restrict__ mspanI,
       float* __restrict__ out, int nb) {
    const int tid  = threadIdx.x;
    const int blk  = blockIdx.x;
    const int lane = tid & 31;
    const int wid  = tid >> 5;
    const int gw   = blk * (NT / 32) + wid;       // global warp id
    const int nwarp = nb * (NT / 32);
    const float NI = __int_as_float(0xff800000);  // -inf

    __shared__ int s_lens[BQ];
    __shared__ double sred[NT];

    // ---- Phase 0: zero outside accumulators; diag init; lens ----
    for (int idx = blk * NT + tid; idx < CHART; idx += nb * NT) {
        g_BL[idx] = 0.f; g_BT[idx] = 0.f;
    }
    if (blk < BQ) {
        const int b = blk;
        if (tid < LQ) {
            float d = lg[((b * LQ) + tid) * LQ + tid];
            g_S [((b * LQ) + tid) * LQ + tid] = d;
            g_ST[((b * LQ) + tid) * LQ + tid] = d;
        }
        // lens from maskspan row 0 (byte/int32 dtype hedge)
        __shared__ int sh[NT];
        sh[tid] = (tid < LQ) ? (int)mspanB[b * LQ * LQ + tid] : 0;
        __syncthreads();
        for (int o = NT / 2; o; o >>= 1) { if (tid < o) sh[tid] += sh[tid + o]; __syncthreads(); }
        int bs = sh[0];
        __syncthreads();
        int len;
        if (bs >= 128) {
            len = bs;                       // bool-as-byte layout
        } else {
            sh[tid] = (tid < LQ) ? mspanI[b * LQ * LQ + tid] : 0;   // int32 layout
            __syncthreads();
            for (int o = NT / 2; o; o >>= 1) { if (tid < o) sh[tid] += sh[tid + o]; __syncthreads(); }
            len = sh[0];
        }
        if (tid == 0) g_lens[b] = len;
    }
    grid_sync(nb);
    if (tid < BQ) s_lens[tid] = g_lens[tid];
    __syncthreads();

    // ---- Phase 1: inside, widths 1..L-1 ----
    for (int w = 1; w < LQ; ++w) {
        const int span = LQ - w;
        const int cells = BQ * span;
        for (int c = gw; c < cells; c += nwarp) {
            const int b = c / span;
            const int i = c - b * span;
            const int j = i + w;
            if (j >= s_lens[b]) continue;

            const float* __restrict__ Lrow = g_S  + ((b * LQ) + i) * LQ + i;
            const float* __restrict__ Rrow = g_ST + ((b * LQ) + j) * LQ + (i + 1);

            float vals[8];
            float vmax = NI;
#pragma unroll
            for (int cc = 0; cc < 8; cc++) {
                int t = lane + cc * 32;
                float v = NI;
                if (t < w) v = Lrow[t] + Rrow[t];
                vals[cc] = v;
                vmax = fmaxf(vmax, v);
            }
            vmax = warp_max(vmax);
            float s = 0.f;
#pragma unroll
            for (int cc = 0; cc < 8; cc++) {
                int t = lane + cc * 32;
                if (t < w) s += __expf(vals[cc] - vmax);
            }
            s = warp_sum(s);
            if (lane == 0) {
                float nv = vmax + __logf(s) + lg[((b * LQ) + i) * LQ + j];
                g_S [((b * LQ) + i) * LQ + j] = nv;
                g_ST[((b * LQ) + j) * LQ + i] = nv;
            }
        }
        grid_sync(nb);
    }

    // ---- Phase 2: outside (reverse-mode in prob domain), widths L-1..1 ----
    // Parent (i, j=i+w) with finalized credit mu distributes
    // mu * exp(s_l + s_r + lg_p - s_p) to children (i,k) [row i of BL] and
    // (k+1,j) [row j of BT]. One parent per BL/BT row per step -> race-free.
    for (int w = LQ - 1; w >= 1; --w) {
        const int span = LQ - w;
        const int cells = BQ * span;
        for (int c = gw; c < cells; c += nwarp) {
            const int b = c / span;
            const int i = c - b * span;
            const int j = i + w;
            const int len = s_lens[b];
            if (j >= len) continue;

            const int pidx = ((b * LQ) + i) * LQ + j;
            float mu = g_BL[pidx] + g_BT[((b * LQ) + j) * LQ + i];
            if (i == 0 && j == len - 1) mu += 1.f;   // root seed
            if (mu == 0.f) continue;

            const float cadd = lg[pidx] - g_S[pidx];
            const float* __restrict__ Lrow = g_S  + ((b * LQ) + i) * LQ + i;
            const float* __restrict__ Rrow = g_ST + ((b * LQ) + j) * LQ + (i + 1);
            float* BLrow = g_BL + ((b * LQ) + i) * LQ + i;
            float* BTrow = g_BT + ((b * LQ) + j) * LQ + (i + 1);

#pragma unroll
            for (int cc = 0; cc < 8; cc++) {
                int t = lane + cc * 32;
                if (t < w) {
                    float e = mu * __expf(Lrow[t] + Rrow[t] + cadd);
                    BLrow[t] += e;
                    BTrow[t] += e;
                }
            }
        }
        grid_sync(nb);
    }

    // ---- Phase 3: fused loss (masks reconstructed from lens) ----
    {
        double a_sp = 0.0, a_ph = 0.0, a_pt = 0.0;
        const int stride = nb * NT;
        for (int idx = blk * NT + tid; idx < CHART; idx += stride) {
            const int b = idx >> 16;
            const int i = (idx >> 8) & 255;
            const int j = idx & 255;
            const int len = s_lens[b];
            if (i < len && j < len) {
                float x = ph[idx];
                float y = (float)ph_ind[idx];
                a_ph += (double)(fmaxf(x, 0.f) + log1pf(expf(-fabsf(x))) - x * y);
                x = pt[idx]; y = (float)pt_ind[idx];
                a_pt += (double)(fmaxf(x, 0.f) + log1pf(expf(-fabsf(x))) - x * y);
                if (i <= j) {
                    float marg = g_BL[idx] + g_BT[((b * LQ) + j) * LQ + i];
                    if (i == 0 && j == len - 1) marg += 1.f;
                    float p = 1.f / (1.f + expf(-ph_arc[idx]));
                    float pm = p * marg;
                    a_sp += (double)((spans_ind[idx] >= 2) ? logf(pm) : logf(1.f - pm));
                }
            }
        }
        sred[tid] = a_sp; __syncthreads();
        for (int o = NT / 2; o; o >>= 1) { if (tid < o) sred[tid] += sred[tid + o]; __syncthreads(); }
        if (tid == 0) g_part[blk * 3 + 0] = sred[0];
        __syncthreads();
        sred[tid] = a_ph; __syncthreads();
        for (int o = NT / 2; o; o >>= 1) { if (tid < o) sred[tid] += sred[tid + o]; __syncthreads(); }
        if (tid == 0) g_part[blk * 3 + 1] = sred[0];
        __syncthreads();
        sred[tid] = a_pt; __syncthreads();
        for (int o = NT / 2; o; o >>= 1) { if (tid < o) sred[tid] += sred[tid + o]; __syncthreads(); }
        if (tid == 0) g_part[blk * 3 + 2] = sred[0];
    }
    grid_sync(nb);

    // ---- Phase 4: final reduction on block 0 ----
    if (blk == 0) {
        double a0 = 0, a1 = 0, a2 = 0;
        for (int p = tid; p < nb; p += NT) {
            a0 += g_part[p * 3 + 0];
            a1 += g_part[p * 3 + 1];
            a2 += g_part[p * 3 + 2];
        }
        __shared__ double r0[NT], r1[NT], r2[NT];
        r0[tid] = a0; r1[tid] = a1; r2[tid] = a2;
        __syncthreads();
        for (int o = NT / 2; o; o >>= 1) {
            if (tid < o) { r0[tid] += r0[tid + o]; r1[tid] += r1[tid + o]; r2[tid] += r2[tid + o]; }
            __syncthreads();
        }
        if (tid == 0) {
            double lens_sum = 0, arc = 0;
            for (int b = 0; b < BQ; b++) {
                double l = (double)s_lens[b];
                lens_sum += l;
                arc += l * l;
            }
            double loss_spans = -r0[0] / lens_sum;
            double loss_ph = r1[0] / arc;
            double loss_pt = r2[0] / arc;
            out[0] = (float)(0.1 * loss_spans + 0.9 * (loss_ph + loss_pt));
        }
    }
}

// ---------------------------------------------------------------------------
extern "C" void kernel_launch(void* const* d_in, const int* in_sizes, int n_in,
                              void* d_out, int out_size) {
    const float* span_logits = (const float*)d_in[0];
    const float* ph          = (const float*)d_in[1];
    const float* pt          = (const float*)d_in[2];
    const float* ph_arc      = (const float*)d_in[3];
    const int*   spans_ind   = (const int*)d_in[4];
    const int*   ph_ind      = (const int*)d_in[5];
    const int*   pt_ind      = (const int*)d_in[6];
    // d_in[7] = maskarc (reconstructed from lens)
    const void*  maskspan    = d_in[8];

    int sm = 148, occ = 1;
    cudaDeviceGetAttribute(&sm, cudaDevAttrMultiProcessorCount, 0);
    cudaOccupancyMaxActiveBlocksPerMultiprocessor(&occ, k_mega, NT, 0);
    if (occ < 1) occ = 1;
    if (occ > 2) occ = 2;            // diminishing returns; cheaper barrier
    int nb = sm * occ;
    if (nb > MAXB) nb = MAXB;

    k_mega<<<nb, NT>>>(span_logits, ph, pt, ph_arc, spans_ind, ph_ind, pt_ind,
                       (const unsigned char*)maskspan, (const int*)maskspan,
                       (float*)d_out, nb);
}

// round 3
// speedup vs baseline: 1.0129x; 1.0129x over previous
#include <cuda_runtime.h>
#include <math.h>

// Problem constants (B=16, L=256)
#define LQ 256
#define BQ 16
#define CHART (BQ * LQ * LQ)
#define NT 512            // threads per block
#define MAXB 1024         // max blocks we size scratch for

// Scratch (no allocation allowed -> __device__ globals)
// g_S  : inside chart s[b,i,j]           (row-major)
// g_ST : transposed inside chart         sT[b,j,i] = s[b,i,j]
// g_BL : outside credit as LEFT child    [b,i,k]
// g_BT : outside credit as RIGHT child   (transposed) [b,j,k+1]
// marginal(i,j) = g_BL[b,i,j] + g_BT[b,j,i] (+1 at root (0,len-1))
__device__ float g_S[CHART];
__device__ float g_ST[CHART];
__device__ float g_BL[CHART];
__device__ float g_BT[CHART];
__device__ int   g_lens[BQ];
__device__ double g_part[MAXB * 3];

// software grid barrier state (gen persists across graph replays; equality-spin is safe)
__device__ unsigned g_arrive;
__device__ volatile unsigned g_gen;

__device__ __forceinline__ void grid_sync(int nb) {
    __threadfence();      // every thread makes its writes visible device-wide
    __syncthreads();
    if (threadIdx.x == 0) {
        unsigned gen = g_gen;
        if (atomicAdd(&g_arrive, 1u) == (unsigned)nb - 1u) {
            g_arrive = 0u;
            __threadfence();
            g_gen = gen + 1u;
        } else {
            while (g_gen == gen) __nanosleep(64);
        }
        __threadfence();
    }
    __syncthreads();
}

__device__ __forceinline__ float warp_max(float v) {
#pragma unroll
    for (int o = 16; o; o >>= 1) v = fmaxf(v, __shfl_xor_sync(0xffffffffu, v, o));
    return v;
}
__device__ __forceinline__ float warp_sum(float v) {
#pragma unroll
    for (int o = 16; o; o >>= 1) v += __shfl_xor_sync(0xffffffffu, v, o);
    return v;
}

// ---------------------------------------------------------------------------
// One persistent kernel: init -> inside (255 steps) -> outside (255 steps)
// -> fused loss reduction. Grid barriers between dependent phases/steps.
__global__ void __launch_bounds__(NT)
k_mega(const float* __restrict__ lg,
       const float* __restrict__ ph, const float* __restrict__ pt,
       const float* __restrict__ ph_arc,
       const int* __restrict__ spans_ind,
       const int* __restrict__ ph_ind, const int* __restrict__ pt_ind,
       const unsigned char* __restrict__ mspanB, const int* __restrict__ mspanI,
       float* __restrict__ out, int nb) {
    const int tid  = threadIdx.x;
    const int blk  = blockIdx.x;
    const int lane = tid & 31;
    const int wid  = tid >> 5;
    const int gw   = blk * (NT / 32) + wid;       // global warp id
    const int nwarp = nb * (NT / 32);
    const float NI = __int_as_float(0xff800000);  // -inf

    __shared__ int s_lens[BQ];
    __shared__ double sred[NT];

    // ---- Phase 0: zero outside accumulators; diag init; lens ----
    for (int idx = blk * NT + tid; idx < CHART; idx += nb * NT) {
        g_BL[idx] = 0.f; g_BT[idx] = 0.f;
    }
    if (blk < BQ) {
        const int b = blk;
        if (tid < LQ) {
            float d = lg[((b * LQ) + tid) * LQ + tid];
            g_S [((b * LQ) + tid) * LQ + tid] = d;
            g_ST[((b * LQ) + tid) * LQ + tid] = d;
        }
        // lens from maskspan row 0 (byte/int32 dtype hedge)
        __shared__ int sh[NT];
        sh[tid] = (tid < LQ) ? (int)mspanB[b * LQ * LQ + tid] : 0;
        __syncthreads();
        for (int o = NT / 2; o; o >>= 1) { if (tid < o) sh[tid] += sh[tid + o]; __syncthreads(); }
        int bs = sh[0];
        __syncthreads();
        int len;
        if (bs >= 128) {
            len = bs;                       // bool-as-byte layout
        } else {
            sh[tid] = (tid < LQ) ? mspanI[b * LQ * LQ + tid] : 0;   // int32 layout
            __syncthreads();
            for (int o = NT / 2; o; o >>= 1) { if (tid < o) sh[tid] += sh[tid + o]; __syncthreads(); }
            len = sh[0];
        }
        if (tid == 0) g_lens[b] = len;
    }
    grid_sync(nb);
    if (tid < BQ) s_lens[tid] = g_lens[tid];
    __syncthreads();

    // ---- Phase 1: inside, widths 1..L-1 ----
    for (int w = 1; w < LQ; ++w) {
        const int span = LQ - w;
        const int cells = BQ * span;
        for (int c = gw; c < cells; c += nwarp) {
            const int b = c / span;
            const int i = c - b * span;
            const int j = i + w;
            if (j >= s_lens[b]) continue;

            const float* __restrict__ Lrow = g_S  + ((b * LQ) + i) * LQ + i;
            const float* __restrict__ Rrow = g_ST + ((b * LQ) + j) * LQ + (i + 1);

            float vals[8];
            float vmax = NI;
#pragma unroll
            for (int cc = 0; cc < 8; cc++) {
                int t = lane + cc * 32;
                float v = NI;
                if (t < w) v = Lrow[t] + Rrow[t];
                vals[cc] = v;
                vmax = fmaxf(vmax, v);
            }
            vmax = warp_max(vmax);
            float s = 0.f;
#pragma unroll
            for (int cc = 0; cc < 8; cc++) {
                int t = lane + cc * 32;
                if (t < w) s += __expf(vals[cc] - vmax);
            }
            s = warp_sum(s);
            if (lane == 0) {
                float nv = vmax + __logf(s) + lg[((b * LQ) + i) * LQ + j];
                g_S [((b * LQ) + i) * LQ + j] = nv;
                g_ST[((b * LQ) + j) * LQ + i] = nv;
            }
        }
        grid_sync(nb);
    }

    // ---- Phase 2: outside (reverse-mode in prob domain), widths L-1..1 ----
    // Parent (i, j=i+w) with finalized credit mu distributes
    // mu * exp(s_l + s_r + lg_p - s_p) to children (i,k) [row i of BL] and
    // (k+1,j) [row j of BT]. One parent per BL/BT row per step -> race-free.
    for (int w = LQ - 1; w >= 1; --w) {
        const int span = LQ - w;
        const int cells = BQ * span;
        for (int c = gw; c < cells; c += nwarp) {
            const int b = c / span;
            const int i = c - b * span;
            const int j = i + w;
            const int len = s_lens[b];
            if (j >= len) continue;

            const int pidx = ((b * LQ) + i) * LQ + j;
            float mu = g_BL[pidx] + g_BT[((b * LQ) + j) * LQ + i];
            if (i == 0 && j == len - 1) mu += 1.f;   // root seed
            if (mu == 0.f) continue;

            const float cadd = lg[pidx] - g_S[pidx];
            const float* __restrict__ Lrow = g_S  + ((b * LQ) + i) * LQ + i;
            const float* __restrict__ Rrow = g_ST + ((b * LQ) + j) * LQ + (i + 1);
            float* BLrow = g_BL + ((b * LQ) + i) * LQ + i;
            float* BTrow = g_BT + ((b * LQ) + j) * LQ + (i + 1);

#pragma unroll
            for (int cc = 0; cc < 8; cc++) {
                int t = lane + cc * 32;
                if (t < w) {
                    float e = mu * __expf(Lrow[t] + Rrow[t] + cadd);
                    BLrow[t] += e;
                    BTrow[t] += e;
                }
            }
        }
        grid_sync(nb);
    }

    // ---- Phase 3: fused loss (masks reconstructed from lens) ----
    {
        double a_sp = 0.0, a_ph = 0.0, a_pt = 0.0;
        const int stride = nb * NT;
        for (int idx = blk * NT + tid; idx < CHART; idx += stride) {
            const int b = idx >> 16;
            const int i = (idx >> 8) & 255;
            const int j = idx & 255;
            const int len = s_lens[b];
            if (i < len && j < len) {
                float x = ph[idx];
                float y = (float)ph_ind[idx];
                a_ph += (double)(fmaxf(x, 0.f) + log1pf(expf(-fabsf(x))) - x * y);
                x = pt[idx]; y = (float)pt_ind[idx];
                a_pt += (double)(fmaxf(x, 0.f) + log1pf(expf(-fabsf(x))) - x * y);
                if (i <= j) {
                    float marg = g_BL[idx] + g_BT[((b * LQ) + j) * LQ + i];
                    if (i == 0 && j == len - 1) marg += 1.f;
                    float p = 1.f / (1.f + expf(-ph_arc[idx]));
                    float pm = p * marg;
                    a_sp += (double)((spans_ind[idx] >= 2) ? logf(pm) : logf(1.f - pm));
                }
            }
        }
        sred[tid] = a_sp; __syncthreads();
        for (int o = NT / 2; o; o >>= 1) { if (tid < o) sred[tid] += sred[tid + o]; __syncthreads(); }
        if (tid == 0) g_part[blk * 3 + 0] = sred[0];
        __syncthreads();
        sred[tid] = a_ph; __syncthreads();
        for (int o = NT / 2; o; o >>= 1) { if (tid < o) sred[tid] += sred[tid + o]; __syncthreads(); }
        if (tid == 0) g_part[blk * 3 + 1] = sred[0];
        __syncthreads();
        sred[tid] = a_pt; __syncthreads();
        for (int o = NT / 2; o; o >>= 1) { if (tid < o) sred[tid] += sred[tid + o]; __syncthreads(); }
        if (tid == 0) g_part[blk * 3 + 2] = sred[0];
    }
    grid_sync(nb);

    // ---- Phase 4: final reduction on block 0 ----
    if (blk == 0) {
        double a0 = 0, a1 = 0, a2 = 0;
        for (int p = tid; p < nb; p += NT) {
            a0 += g_part[p * 3 + 0];
            a1 += g_part[p * 3 + 1];
            a2 += g_part[p * 3 + 2];
        }
        __shared__ double r0[NT], r1[NT], r2[NT];
        r0[tid] = a0; r1[tid] = a1; r2[tid] = a2;
        __syncthreads();
        for (int o = NT / 2; o; o >>= 1) {
            if (tid < o) { r0[tid] += r0[tid + o]; r1[tid] += r1[tid + o]; r2[tid] += r2[tid + o]; }
            __syncthreads();
        }
        if (tid == 0) {
            double lens_sum = 0, arc = 0;
            for (int b = 0; b < BQ; b++) {
                double l = (double)s_lens[b];
                lens_sum += l;
                arc += l * l;
            }
            double loss_spans = -r0[0] / lens_sum;
            double loss_ph = r1[0] / arc;
            double loss_pt = r2[0] / arc;
            out[0] = (float)(0.1 * loss_spans + 0.9 * (loss_ph + loss_pt));
        }
    }
}

// ---------------------------------------------------------------------------
extern "C" void kernel_launch(void* const* d_in, const int* in_sizes, int n_in,
                              void* d_out, int out_size) {
    const float* span_logits = (const float*)d_in[0];
    const float* ph          = (const float*)d_in[1];
    const float* pt          = (const float*)d_in[2];
    const float* ph_arc      = (const float*)d_in[3];
    const int*   spans_ind   = (const int*)d_in[4];
    const int*   ph_ind      = (const int*)d_in[5];
    const int*   pt_ind      = (const int*)d_in[6];
    // d_in[7] = maskarc (reconstructed from lens)
    const void*  maskspan    = d_in[8];

    int sm = 148, occ = 1;
    cudaDeviceGetAttribute(&sm, cudaDevAttrMultiProcessorCount, 0);
    cudaOccupancyMaxActiveBlocksPerMultiprocessor(&occ, k_mega, NT, 0);
    if (occ < 1) occ = 1;
    if (occ > 2) occ = 2;            // diminishing returns; cheaper barrier
    int nb = sm * occ;
    if (nb > MAXB) nb = MAXB;

    k_mega<<<nb, NT>>>(span_logits, ph, pt, ph_arc, spans_ind, ph_ind, pt_ind,
                       (const unsigned char*)maskspan, (const int*)maskspan,
                       (float*)d_out, nb);
}